// round 9
// baseline (speedup 1.0000x reference)
#include <cuda_runtime.h>
#include <cuda_bf16.h>
#include <cstdint>

// PathRaster2d R9: zeros-first + STG.256 at the measured-best grid size.
// 1024 blocks (256x16 tiles), 256 threads. Each thread stores 2 x 32B zeros
// via st.global.v8.f32 IMMEDIATELY (no input dependency); kp load + sample
// math + exact point-to-box prune hide under the store drain. Active warps
// (rare) recompute their 16 pixels with the full 32-sample min and overwrite
// (same thread, same address => program-ordered). Per-pixel arithmetic is
// bit-identical to all passing rounds (rel_err 0.0).

#define CANVAS_H 2048
#define CANVAS_W 2048
#define TILE_W 256
#define TILE_H 16

__device__ __forceinline__ void stg256(float* p, const float* v)
{
    asm volatile("st.global.v8.f32 [%0], {%1,%2,%3,%4,%5,%6,%7,%8};"
                 :: "l"(p), "f"(v[0]), "f"(v[1]), "f"(v[2]), "f"(v[3]),
                    "f"(v[4]), "f"(v[5]), "f"(v[6]), "f"(v[7])
                 : "memory");
}

__global__ void __launch_bounds__(256)
path_raster_kernel(const float* __restrict__ kp, float* __restrict__ out)
{
    const int tx = threadIdx.x;          // 0..31 (lane == sample index)
    const int ty = threadIdx.y;          // 0..7
    const int x0 = blockIdx.x * TILE_W;
    const int y0 = blockIdx.y * TILE_H;

    const int x = x0 + tx * 8;           // 8 consecutive floats per thread
    float* base = out + (size_t)(y0 + ty) * CANVAS_W + x;   // rows ty, ty+8

    // ---- phase 1: unconditional zero stores, no input dependency ----
    {
        const float z[8] = {0.f, 0.f, 0.f, 0.f, 0.f, 0.f, 0.f, 0.f};
        stg256(base, z);
        stg256(base + (size_t)8 * CANVAS_W, z);
    }

    // ---- phase 2: samples (hidden under store drain), ref-matched rounding ----
    // t_i = i * fl(1/31), endpoint forced to 1.0 (matches jnp.linspace)
    float t = (tx == 31) ? 1.0f : (float)tx * (1.0f / 31.0f);
    float u = __fsub_rn(1.0f, t);
    float b0 = __fmul_rn(u, u);
    float b1 = __fmul_rn(__fmul_rn(2.0f, t), u);
    float b2 = __fmul_rn(t, t);
    float ky0 = __fmul_rn(__ldg(kp + 0), 2048.0f), kx0 = __fmul_rn(__ldg(kp + 1), 2048.0f);
    float ky1 = __fmul_rn(__ldg(kp + 2), 2048.0f), kx1 = __fmul_rn(__ldg(kp + 3), 2048.0f);
    float ky2 = __fmul_rn(__ldg(kp + 4), 2048.0f), kx2 = __fmul_rn(__ldg(kp + 5), 2048.0f);
    float py = __fadd_rn(__fadd_rn(__fmul_rn(b0, ky0), __fmul_rn(b1, ky1)),
                         __fmul_rn(b2, ky2));
    float px = __fadd_rn(__fadd_rn(__fmul_rn(b0, kx0), __fmul_rn(b1, kx1)),
                         __fmul_rn(b2, kx2));

    // Exact point-to-tile-box distance; squared threshold 4.5 (> 4.0) pads for
    // rounding — only ever KEEPS extra samples (dist(pixel,s) >= boxdist(s),
    // so a sample with boxdist >= 2 can never decide a nonzero pixel here).
    float bdy = fmaxf(fmaxf((float)y0 - py, py - (float)(y0 + TILE_H - 1)), 0.0f);
    float bdx = fmaxf(fmaxf((float)x0 - px, px - (float)(x0 + TILE_W - 1)), 0.0f);
    bool near = (bdy * bdy + bdx * bdx) < 4.5f;
    unsigned mask = __ballot_sync(0xffffffffu, near);

    if (mask == 0u) return;              // 99.9% of warps: done

    // ---- phase 3 (rare): full min for this thread's 16 pixels, overwrite ----
    const float maxd = sqrtf(2048.0f * 2048.0f + 2048.0f * 2048.0f);
    float fx[8];
    #pragma unroll
    for (int i = 0; i < 8; i++) fx[i] = (float)(x + i);
    #pragma unroll
    for (int r = 0; r < 2; r++) {
        const float fy = (float)(y0 + ty + r * 8);
        float m[8];
        #pragma unroll
        for (int i = 0; i < 8; i++) m[i] = 3.4e38f;
        unsigned mm = mask;              // warp-uniform loop
        while (mm) {
            int lane = __ffs(mm) - 1;
            mm &= mm - 1u;
            float syv = __shfl_sync(0xffffffffu, py, lane);
            float sxv = __shfl_sync(0xffffffffu, px, lane);
            float dy  = __fsub_rn(fy, syv);
            float dy2 = __fmul_rn(dy, dy);   // separate op, matches reference
            #pragma unroll
            for (int i = 0; i < 8; i++) {
                float d = __fsub_rn(fx[i], sxv);
                m[i] = fminf(m[i], __fadd_rn(dy2, __fmul_rn(d, d)));
            }
        }
        // sqrt BEFORE compare (boundary rounding identical to reference)
        float v[8];
        #pragma unroll
        for (int i = 0; i < 8; i++) {
            float d = sqrtf(m[i]);
            v[i] = (d < 2.0f) ? __fsub_rn(1.0f, __fdiv_rn(d, maxd)) : 0.0f;
        }
        stg256(base + (size_t)(r * 8) * CANVAS_W, v);
    }
}

extern "C" void kernel_launch(void* const* d_in, const int* in_sizes, int n_in,
                              void* d_out, int out_size)
{
    const float* kp = (const float*)d_in[0];   // [3,2] normalized (y,x)
    float* out = (float*)d_out;                // [2048,2048] fp32

    dim3 block(32, 8);
    dim3 grid(CANVAS_W / TILE_W, CANVAS_H / TILE_H);  // (8, 128) = 1024 blocks
    path_raster_kernel<<<grid, block>>>(kp, out);
}